// round 4
// baseline (speedup 1.0000x reference)
#include <cuda_runtime.h>
#include <cstdint>

// DeepInsightEncoding: out[b,h,w,c] for c in {stamp, scatter, rowcopy, nd, bars}
// B=512, D=32, H=W=128. Output fp32 [512,128,128,5] = 168 MB -> HBM-write bound.
//
// Grid: one CTA per half-image (64 rows) => 1024 CTAs, 32KB smem di-map each,
// 7 CTAs/SM => ~1036 concurrent => single wave.
// Each thread handles 4 consecutive pixels (w..w+3, w%4==0): 5 aligned float4 stores.

#define THREADS 256
#define ROWS_PER_CTA 64

__global__ void __launch_bounds__(THREADS)
deepinsight_kernel(const float* __restrict__ inputs,   // [512,32]
                   const float* __restrict__ stamp,    // [128,128]
                   const int*   __restrict__ coords,   // [32,2] (row, col)
                   float*       __restrict__ out)      // [512,128,128,5]
{
    __shared__ float  di[ROWS_PER_CTA * 128];  // 32 KB scatter map for this half-image
    __shared__ float  sx[32];
    __shared__ int    sbarh[32];
    __shared__ signed char sc2b[128];
    __shared__ float  s_inv_range;

    const int b   = blockIdx.x >> 1;
    const int h0  = (blockIdx.x & 1) * ROWS_PER_CTA;
    const int tid = threadIdx.x;

    // --- per-batch scalars ---
    if (tid < 32) {
        float v = inputs[b * 32 + tid];
        sx[tid] = v;
        int bh = (int)rintf(v * 128.0f);      // round-half-even, matches jnp.round
        bh = min(max(bh, 0), 128);
        sbarh[tid] = bh;
        // warp reduction for min/max (range of pairwise |xi-xj| = max - min; min of dm = 0)
        float mn = v, mx = v;
        #pragma unroll
        for (int o = 16; o; o >>= 1) {
            mn = fminf(mn, __shfl_xor_sync(0xffffffffu, mn, o));
            mx = fmaxf(mx, __shfl_xor_sync(0xffffffffu, mx, o));
        }
        if (tid == 0) s_inv_range = 1.0f / (mx - mn);
    }
    // col -> bar index: bar_w=1, gap=2, first bar col = 17, stride 3, 32 bars
    if (tid < 128) {
        int t = tid - 17;
        signed char bar = -1;
        if (t >= 0 && t <= 93 && (t % 3) == 0) bar = (signed char)(t / 3);
        sc2b[tid] = bar;
    }
    // zero the scatter map (32 KB / 16 B = 2048 float4; 8 per thread)
    {
        float4* di4 = (float4*)di;
        #pragma unroll
        for (int i = tid; i < (ROWS_PER_CTA * 128) / 4; i += THREADS)
            di4[i] = make_float4(0.f, 0.f, 0.f, 0.f);
    }
    __syncthreads();

    // scatter (duplicates sum, matching tf.scatter_nd semantics)
    if (tid < 32) {
        int r = coords[2 * tid];
        int c = coords[2 * tid + 1];
        if (r >= h0 && r < h0 + ROWS_PER_CTA)
            atomicAdd(&di[(r - h0) * 128 + c], sx[tid]);
    }
    __syncthreads();

    const float inv_range = s_inv_range;

    // 64 rows x 128 cols = 8192 pixels => 2048 groups of 4 => 8 groups/thread
    #pragma unroll 4
    for (int g = tid; g < (ROWS_PER_CTA * 128) / 4; g += THREADS) {
        const int hl = g >> 5;             // local row
        const int h  = h0 + hl;
        const int w4 = (g & 31) << 2;      // start col (multiple of 4)

        const float rc  = sx[h >> 2];                                 // rowcopy
        const float ndv = fabsf(rc - sx[w4 >> 2]) * inv_range;        // nd (w..w+3 share w>>2)

        const float4 s4 = *(const float4*)(stamp + h * 128 + w4);
        const float4 d4 = *(const float4*)(&di[hl * 128 + w4]);

        float bar[4];
        #pragma unroll
        for (int k = 0; k < 4; k++) {
            int bi = sc2b[w4 + k];
            bar[k] = (bi >= 0 && h < sbarh[bi]) ? 1.0f : 0.0f;
        }

        // 4 pixels * 5 channels = 20 floats = 5 aligned float4 stores
        float4* o = (float4*)(out + ((size_t)(b * 128 + h) * 128 + w4) * 5);
        o[0] = make_float4(s4.x,   d4.x,   rc,     ndv);
        o[1] = make_float4(bar[0], s4.y,   d4.y,   rc);
        o[2] = make_float4(ndv,    bar[1], s4.z,   d4.z);
        o[3] = make_float4(rc,     ndv,    bar[2], s4.w);
        o[4] = make_float4(d4.w,   rc,     ndv,    bar[3]);
    }
}

extern "C" void kernel_launch(void* const* d_in, const int* in_sizes, int n_in,
                              void* d_out, int out_size)
{
    const float* inputs = (const float*)d_in[0];   // [512,32]
    const float* stamp  = (const float*)d_in[1];   // [128,128,1]
    const int*   coords = (const int*)d_in[2];     // [32,2]
    float*       out    = (float*)d_out;           // [512,128,128,5]

    deepinsight_kernel<<<512 * 2, THREADS>>>(inputs, stamp, coords, out);
}